// round 15
// baseline (speedup 1.0000x reference)
#include <cuda_runtime.h>
#include <math.h>
#include <stdint.h>

#define PI_D 3.14159265358979323846

// B_IN=64, B_OUT=20, B_INV=20, BATCH=16, F_IN=16, F_OUT=32, N_GRID=24
// half-pair count: sum_l (l+1)(2l+1) = 5530

__constant__ int c_hoff[20]  = {0,1,7,22,50,95,161,252,372,525,715,946,1222,1547,1925,2360,2856,3417,4047,4750};
__constant__ int c_hstep[20] = {1,6,15,28,45,66,91,120,153,190,231,276,325,378,435,496,561,630,703,780};

__device__ float  g_ws2[128*400];      // [beta_b][lm]  lm = l*l + (m+l)
__device__ float2 g_cFk[24*400];       // conj(F_k) [p][lm]
__device__ float4 g_dhA[5*5530];       // (2l+1)*d, betas bg*8+0..3, [bg][hpair]
__device__ float4 g_dhB[5*5530];       // betas bg*8+4..7
__device__ unsigned int g_pinfo[5530]; // (l<<12)|(m<<6)|ni
__device__ float2 g_tw[128*20];        // [a][m] e^{-2pi i a m/128}
__device__ float2 g_Xf[20*128*256];    // [m][b][zi]
__device__ float2 g_xl[16*400*16];     // [z][lm][i]
__device__ float2 g_cy[32*400*16];     // [o][lm][i]
__device__ float2 g_zl[512*5530];      // [zo][hpair]

// e^{+2pi i k/40} tables (static-index use only -> folded to immediates)
__device__ static constexpr float TWC[40] = {
 1.0f, 0.98768834f, 0.95105652f, 0.89100652f, 0.80901699f, 0.70710678f,
 0.58778525f, 0.45399050f, 0.30901699f, 0.15643447f, 0.0f, -0.15643447f,
 -0.30901699f, -0.45399050f, -0.58778525f, -0.70710678f, -0.80901699f,
 -0.89100652f, -0.95105652f, -0.98768834f, -1.0f, -0.98768834f, -0.95105652f,
 -0.89100652f, -0.80901699f, -0.70710678f, -0.58778525f, -0.45399050f,
 -0.30901699f, -0.15643447f, 0.0f, 0.15643447f, 0.30901699f, 0.45399050f,
 0.58778525f, 0.70710678f, 0.80901699f, 0.89100652f, 0.95105652f, 0.98768834f };
__device__ static constexpr float TWS[40] = {
 0.0f, 0.15643447f, 0.30901699f, 0.45399050f, 0.58778525f, 0.70710678f,
 0.80901699f, 0.89100652f, 0.95105652f, 0.98768834f, 1.0f, 0.98768834f,
 0.95105652f, 0.89100652f, 0.80901699f, 0.70710678f, 0.58778525f,
 0.45399050f, 0.30901699f, 0.15643447f, 0.0f, -0.15643447f, -0.30901699f,
 -0.45399050f, -0.58778525f, -0.70710678f, -0.80901699f, -0.89100652f,
 -0.95105652f, -0.98768834f, -1.0f, -0.98768834f, -0.95105652f, -0.89100652f,
 -0.80901699f, -0.70710678f, -0.58778525f, -0.45399050f, -0.30901699f,
 -0.15643447f };
// e^{+2pi i k/8}
__device__ static constexpr float W8C[8] = {1.f,0.70710678f,0.f,-0.70710678f,-1.f,-0.70710678f,0.f,0.70710678f};
__device__ static constexpr float W8S[8] = {0.f,0.70710678f,1.f,0.70710678f,0.f,-0.70710678f,-1.f,-0.70710678f};

__device__ __forceinline__ float2 cadd(float2 a, float2 b){ return make_float2(a.x+b.x, a.y+b.y); }
__device__ __forceinline__ float2 csub(float2 a, float2 b){ return make_float2(a.x-b.x, a.y-b.y); }
__device__ __forceinline__ float2 cmuli(float2 a){ return make_float2(-a.y, a.x); }      // *i
__device__ __forceinline__ float2 cmulni(float2 a){ return make_float2(a.y, -a.x); }     // *(-i)
__device__ __forceinline__ float2 cmulc(float2 a, float c, float s){                     // *(c+is)
    return make_float2(a.x*c - a.y*s, a.x*s + a.y*c);
}

// store one (beta, hpair) value into the split coalesced d-tables
__device__ __forceinline__ void store_d(int b, int hidx, float v) {
    int bb = b & 7, bgi = b >> 3;
    if (bb < 4) ((float*)&g_dhA[bgi*5530 + hidx])[bb] = v;
    else        ((float*)&g_dhB[bgi*5530 + hidx])[bb - 4] = v;
}

// ---------- fp32 Wigner-d: log-space seed + upward 3-term recurrence ----------
__device__ __forceinline__ float wseed(int m, int n, float lcb, float lsb, const float* lf) {
    int am = m < 0 ? -m : m, an = n < 0 ? -n : n;
    int l = am > an ? am : an;
    float v;
    if (am >= an) {
        float lc = 0.5f*(lf[2*l] - lf[l+n] - lf[l-n]);
        if (m >= 0) { v = expf(lc + (l+n)*lcb + (l-n)*lsb); if ((l-n)&1) v = -v; }
        else        { v = expf(lc + (l-n)*lcb + (l+n)*lsb); }
    } else {
        float lc = 0.5f*(lf[2*l] - lf[l+m] - lf[l-m]);
        if (n >= 0) { v = expf(lc + (l+m)*lcb + (l-m)*lsb); }
        else        { v = expf(lc + (l-m)*lcb + (l+m)*lsb); if ((l+m)&1) v = -v; }
    }
    return v;
}

// ---------- combined init kernel ----------
__global__ void k_init() {
    __shared__ float lf[41];
    __shared__ double sterm[64];
    __shared__ double swq;
    int t = threadIdx.x;
    if (t <= 40) lf[t] = lgammaf((float)(t + 1));
    int blk = blockIdx.x;

    if (blk < 128) {
        int b = blk;
        double beta = PI_D * (2.0*b + 1.0) / 256.0;
        if (t < 64) sterm[t] = sin((2.0*t + 1.0) * beta) / (2.0*t + 1.0);
        __syncthreads();
        if (t == 0) {
            double acc = 0.0;
            for (int k = 0; k < 64; k++) acc += sterm[k];
            swq = (2.0/64.0) * sin(beta) * acc;
        }
        __syncthreads();
        float w = (float)swq;
        float cb = (float)cos(beta*0.5), sb = (float)sin(beta*0.5);
        float cosb = (float)cos(beta);
        float lcb = logf(cb), lsb = logf(sb);
        if (t < 39) {
            int m = t - 19;
            int am = m < 0 ? -m : m;
            int l0 = am;
            float d1 = wseed(m, 0, lcb, lsb, lf), d2 = 0.0f;
            g_ws2[b*400 + l0*l0 + l0 + m] = d1 * w;
            int jstart = l0 + 1;
            if (l0 == 0) {
                d2 = d1; d1 = cosb;
                g_ws2[b*400 + 2] = d1 * w;
                jstart = 2;
            }
            for (int j = jstart; j <= 19; j++) {
                float wj  = sqrtf((float)((j*j - m*m) * (j*j)));
                float wj1 = sqrtf((float)(((j-1)*(j-1) - m*m) * ((j-1)*(j-1))));
                float d = ((2*j-1)*((float)(j*(j-1))*cosb) * d1 - (float)j*wj1*d2) / ((float)(j-1)*wj);
                g_ws2[b*400 + j*j + j + m] = d * w;
                d2 = d1; d1 = d;
            }
        }
    } else if (blk < 152) {
        int p = blk - 128;
        __syncthreads();
        double beta  = ((p >> 3) + 1) * PI_D / 24.0;
        float cb = (float)cos(beta*0.5), sb = (float)sin(beta*0.5);
        float cosb = (float)cos(beta);
        float lcb = logf(cb), lsb = logf(sb);
        if (t < 39) {
            int m = t - 19;
            int am = m < 0 ? -m : m;
            int l0 = am;
            float cph, sph;
            sincospif((float)(m * (p & 7)) * 0.25f, &sph, &cph);
            float d1 = wseed(m, 0, lcb, lsb, lf), d2 = 0.0f;
            g_cFk[p*400 + l0*l0 + l0 + m] = make_float2(d1*cph, d1*sph);
            int jstart = l0 + 1;
            if (l0 == 0) {
                d2 = d1; d1 = cosb;
                g_cFk[p*400 + 2] = make_float2(d1*cph, d1*sph);
                jstart = 2;
            }
            for (int j = jstart; j <= 19; j++) {
                float wj  = sqrtf((float)((j*j - m*m) * (j*j)));
                float wj1 = sqrtf((float)(((j-1)*(j-1) - m*m) * ((j-1)*(j-1))));
                float d = ((2*j-1)*((float)(j*(j-1))*cosb) * d1 - (float)j*wj1*d2) / ((float)(j-1)*wj);
                g_cFk[p*400 + j*j + j + m] = make_float2(d*cph, d*sph);
                d2 = d1; d1 = d;
            }
        }
    } else if (blk < 192) {
        int b = blk - 152;
        __syncthreads();
        double beta = PI_D * (2.0*b + 1.0) / 80.0;
        float cb = (float)cos(beta*0.5), sb = (float)sin(beta*0.5);
        float cosb = (float)cos(beta);
        float lcb = logf(cb), lsb = logf(sb);
        for (int p = t; p < 780; p += blockDim.x) {
            int m = p / 39, nj = p % 39, n = nj - 19;
            int an = n < 0 ? -n : n;
            int l0 = m > an ? m : an;
            float d1 = wseed(m, n, lcb, lsb, lf), d2 = 0.0f;
            store_d(b, c_hoff[l0] + m*(2*l0+1) + n + l0, (float)(2*l0+1) * d1);
            int jstart = l0 + 1;
            if (l0 == 0) {
                d2 = d1; d1 = cosb;
                store_d(b, c_hoff[1] + 1, 3.0f * d1);
                jstart = 2;
            }
            float mn = (float)(m * n);
            for (int j = jstart; j <= 19; j++) {
                float wj  = sqrtf((float)((j*j - m*m) * (j*j - n*n)));
                float wj1 = sqrtf((float)(((j-1)*(j-1) - m*m) * ((j-1)*(j-1) - n*n)));
                float d = ((2*j-1)*((float)(j*(j-1))*cosb - mn) * d1 - (float)j*wj1*d2) / ((float)(j-1)*wj);
                store_d(b, c_hoff[j] + m*(2*j+1) + n + j, (float)(2*j+1) * d);
                d2 = d1; d1 = d;
            }
        }
    } else {
        __syncthreads();
        for (int p = t; p < 5530; p += blockDim.x) {
            int l = 0, acc = 0;
            for (; l < 20; l++) {
                int sz = (l+1)*(2*l+1);
                if (p < acc + sz) break;
                acc += sz;
            }
            int r = p - acc, w = 2*l + 1;
            g_pinfo[p] = (unsigned)((l << 12) | ((r / w) << 6) | (r % w));
        }
        for (int idx = t; idx < 2560; idx += blockDim.x) {
            int a = idx / 20, m = idx % 20;
            float s, c;
            sincospif(-(float)(a * m) / 64.0f, &s, &c);
            g_tw[idx] = make_float2(c, s);
        }
    }
}

// ---------- K1: truncated real DFT over alpha via twiddle table ----------
__global__ void k_dft(const float* __restrict__ x) {
    __shared__ float  xs[16][130];
    __shared__ float2 tws[128*20];
    int bg = blockIdx.x, zi = blockIdx.y;
    const float* xp = x + (zi * 128 + bg * 16) * 128;
    for (int idx = threadIdx.x; idx < 2048; idx += 160)
        xs[idx >> 7][idx & 127] = xp[idx];
    for (int idx = threadIdx.x; idx < 2560; idx += 160)
        tws[idx] = g_tw[idx];
    __syncthreads();
    int bp = threadIdx.x / 20;
    int m  = threadIdx.x % 20;
    const float* r0 = xs[2*bp];
    const float* r1 = xs[2*bp + 1];
    float a0r = 0.f, a0i = 0.f, a1r = 0.f, a1i = 0.f;
    #pragma unroll 4
    for (int a = 0; a < 128; a++) {
        float2 w = tws[a*20 + m];
        float x0 = r0[a], x1 = r1[a];
        a0r += x0*w.x; a0i += x0*w.y;
        a1r += x1*w.x; a1i += x1*w.y;
    }
    int b = bg * 16 + 2*bp;
    g_Xf[(m*128 + b    )*256 + zi] = make_float2(a0r, a0i);
    g_Xf[(m*128 + b + 1)*256 + zi] = make_float2(a1r, a1i);
}

// ---------- K2: S2 analysis tiled by (|m|, z), with k_cy work fused as extra blocks ----------
__global__ void k_xl2cy(const float* __restrict__ kern) {
    __shared__ float2 Xs[128*16];
    __shared__ float wsp[128*20];
    __shared__ float wsm[128*20];
    __shared__ float2 sF[24];
    int t = threadIdx.x;
    if (blockIdx.x >= 20) {
        // ---- cy path ----
        int lm = (blockIdx.x - 20) * 16 + blockIdx.y;
        if (t < 24) sF[t] = g_cFk[t * 400 + lm];
        __syncthreads();
        int i = t >> 5, o = t & 31;
        const float* kp = kern + (i * 32 + o) * 24;
        float ar = 0.0f, ai = 0.0f;
        for (int p = 0; p < 24; p++) {
            float k = kp[p];
            ar += k * sF[p].x; ai += k * sF[p].y;
        }
        const float S = 0.00816496580927726f;
        g_cy[((size_t)o * 400 + lm) * 16 + i] = make_float2(ar * S, ai * S);
        return;
    }
    // ---- xl2 path ----
    int ma = blockIdx.x, z = blockIdx.y;
    int nl = 20 - ma;
    for (int idx = t; idx < 2048; idx += 512) {
        int b = idx >> 4, i = idx & 15;
        Xs[idx] = g_Xf[(ma*128 + b)*256 + z*16 + i];
    }
    for (int idx = t; idx < 128*nl; idx += 512) {
        int b = idx / nl, li = idx % nl;
        int l = ma + li;
        wsp[idx] = g_ws2[b*400 + l*l + l + ma];
        if (ma > 0) wsm[idx] = g_ws2[b*400 + l*l + l - ma];
    }
    __syncthreads();
    for (int item = t; item < nl*16; item += 512) {
        int li = item >> 4, i = item & 15;
        int l = ma + li;
        float pr = 0.f, pi = 0.f, mr = 0.f, mi = 0.f;
        for (int b = 0; b < 128; b++) {
            float2 xv = Xs[b*16 + i];
            float wp = wsp[b*nl + li];
            pr += wp * xv.x; pi += wp * xv.y;
            if (ma > 0) {
                float wm = wsm[b*nl + li];
                mr += wm * xv.x; mi -= wm * xv.y;
            }
        }
        g_xl[((size_t)z*400 + l*l + l + ma)*16 + i] = make_float2(pr, pi);
        if (ma > 0)
            g_xl[((size_t)z*400 + l*l + l - ma)*16 + i] = make_float2(mr, mi);
    }
}

// ---------- K4: zl[zo][hpair], LDS.128 vectorized ----------
__global__ void k_zl() {
    extern __shared__ float2 sm4[];
    float2* xs = sm4;            // [lm][i] 400*16
    float2* cs = sm4 + 6400;     // [lm][i] pitch 18 (16B-aligned rows)
    int o = blockIdx.x, z = blockIdx.y;
    for (int idx = threadIdx.x; idx < 6400; idx += blockDim.x) {
        xs[idx] = g_xl[(size_t)z * 6400 + idx];
        int lm = idx >> 4, i = idx & 15;
        cs[lm * 18 + i] = g_cy[(size_t)o * 6400 + idx];
    }
    __syncthreads();
    float2* outp = g_zl + (size_t)(z * 32 + o) * 5530;
    for (int p = threadIdx.x; p < 5530; p += blockDim.x) {
        unsigned info = g_pinfo[p];
        int l = info >> 12, m = (info >> 6) & 63, ni = info & 63;
        const float4* A4 = (const float4*)(xs + (l*l + l + m) * 16);
        const float4* B4 = (const float4*)(cs + (l*l + ni) * 18);
        float ar = 0.0f, ai = 0.0f;
        #pragma unroll
        for (int i = 0; i < 8; i++) {
            float4 a = A4[i], c = B4[i];
            ar += a.x*c.x - a.y*c.y;
            ai += a.x*c.y + a.y*c.x;
            ar += a.z*c.z - a.w*c.w;
            ai += a.z*c.w + a.w*c.z;
        }
        outp[p] = make_float2(ar, ai);
    }
}

// ---------- stage1 40-pt FFT partials: T[r][up] for u = 4*HH+up ----------
template<int HH>
__device__ __forceinline__ void fft40_T(const float2* __restrict__ Grow, float2 T[5][4]) {
    const float R2 = 0.70710678f;
    #pragma unroll
    for (int r = 0; r < 5; r++) {
        float2 x0=Grow[r],    x1=Grow[5+r],  x2=Grow[10+r], x3=Grow[15+r];
        float2 x4=Grow[20+r], x5=Grow[25+r], x6=Grow[30+r], x7=Grow[35+r];
        float2 a04=cadd(x0,x4), s04=csub(x0,x4);
        float2 a26=cadd(x2,x6), s26=csub(x2,x6);
        float2 E0=cadd(a04,a26), E1=cadd(s04,cmuli(s26));
        float2 E2=csub(a04,a26), E3=csub(s04,cmuli(s26));
        float2 a15=cadd(x1,x5), s15=csub(x1,x5);
        float2 a37=cadd(x3,x7), s37=csub(x3,x7);
        float2 O0=cadd(a15,a37), O1=cadd(s15,cmuli(s37));
        float2 O2=csub(a15,a37), O3=csub(s15,cmuli(s37));
        float2 w1o = make_float2(R2*(O1.x-O1.y), R2*(O1.x+O1.y));  // W8^1 * O1
        float2 w2o = cmuli(O2);                                     // W8^2 * O2
        float2 w3o = make_float2(-R2*(O3.x+O3.y), R2*(O3.x-O3.y)); // W8^3 * O3
        float2 y0, y1, y2, y3;
        if (HH == 0) { y0=cadd(E0,O0); y1=cadd(E1,w1o); y2=cadd(E2,w2o); y3=cadd(E3,w3o); }
        else         { y0=csub(E0,O0); y1=csub(E1,w1o); y2=csub(E2,w2o); y3=csub(E3,w3o); }
        T[r][0] = cmulc(y0, TWC[(r*(4*HH+0))%40], TWS[(r*(4*HH+0))%40]);
        T[r][1] = cmulc(y1, TWC[(r*(4*HH+1))%40], TWS[(r*(4*HH+1))%40]);
        T[r][2] = cmulc(y2, TWC[(r*(4*HH+2))%40], TWS[(r*(4*HH+2))%40]);
        T[r][3] = cmulc(y3, TWC[(r*(4*HH+3))%40], TWS[(r*(4*HH+3))%40]);
    }
}

// ---------- K5 fused: 2 zo per block (d-reuse), G-build + stage1 + stage2 + output ----------
// two G/H regions of 7040 float2 each -> 112640 B dynamic smem, 2 CTAs/SM
__global__ void __launch_bounds__(320, 2) k_ho(const float* __restrict__ bias,
                                               float* __restrict__ out) {
    extern __shared__ float2 sm5[];
    int zo0 = blockIdx.x;            // 0..255; pair is zo0 and zo0+256 (same o, z and z+8)
    int bg  = blockIdx.y;
    int t = threadIdx.x;

    // phase 1: build G for 8 betas x 2 zo at once (d loaded once, 32 FMAs per d-pair)
    const float2* zrow0 = g_zl + (size_t)zo0 * 5530;
    const float2* zrow1 = g_zl + (size_t)(zo0 + 256) * 5530;
    const float4* dA = g_dhA + bg * 5530;
    const float4* dB = g_dhB + bg * 5530;
    for (int e = t; e < 800; e += 320) {
        int m = e / 40, j = e % 40;
        int n = (j <= 19) ? j : j - 40;
        int an = n < 0 ? -n : n;
        int lmin = m > an ? m : an;
        int idx = c_hoff[lmin] + m*(2*lmin + 1) + (n + lmin);
        int inc = 2*m + 1;
        float gr[16], gi[16];   // [zz*8 + beta]
        #pragma unroll
        for (int k = 0; k < 16; k++) { gr[k] = 0.f; gi[k] = 0.f; }
        for (int l = lmin; l < 20; l++) {
            float2 zv0 = __ldg(zrow0 + idx);
            float2 zv1 = __ldg(zrow1 + idx);
            float4 d0 = __ldg(dA + idx);
            float4 d1 = __ldg(dB + idx);
            float dv[8] = {d0.x,d0.y,d0.z,d0.w,d1.x,d1.y,d1.z,d1.w};
            #pragma unroll
            for (int k = 0; k < 8; k++) {
                gr[k]   += zv0.x*dv[k]; gi[k]   += zv0.y*dv[k];
                gr[8+k] += zv1.x*dv[k]; gi[8+k] += zv1.y*dv[k];
            }
            idx += c_hstep[l] + inc;
        }
        int base = m*41 + j;
        #pragma unroll
        for (int k = 0; k < 8; k++) {
            sm5[       base + k*820] = make_float2(gr[k],   gi[k]);
            sm5[7040 + base + k*820] = make_float2(gr[8+k], gi[8+k]);
        }
    }
    __syncthreads();

    int h = t / 160, row = t - h*160;
    int blocR = row / 20, mR = row % 20;
    float bv = bias[zo0 & 31];

    #pragma unroll
    for (int zz = 0; zz < 2; zz++) {
        float2* Gs = sm5 + zz*7040;
        float2* Hs = Gs;
        int zo = zo0 + zz*256;

        // phase 2a: stage-1 FFT partials in registers
        float2 T[5][4];
        {
            const float2* Grow = Gs + row*41;
            if (h == 0) fft40_T<0>(Grow, T);
            else        fft40_T<1>(Grow, T);
        }
        __syncthreads();   // Gs reads done; region becomes H

        // phase 2b: combine + write H (pitch 22)
        {
            float2* dsts = Hs + blocR*880 + mR;
            #pragma unroll
            for (int up = 0; up < 4; up++) {
                int u = 4*h + up;
                #pragma unroll
                for (int s = 0; s < 5; s++) {
                    float2 acc = T[0][up];
                    #pragma unroll
                    for (int r = 1; r < 5; r++)
                        acc = cadd(acc, cmulc(T[r][up], TWC[(8*r*s)%40], TWS[(8*r*s)%40]));
                    dsts[(8*s + u) * 22] = acc;
                }
            }
        }
        __syncthreads();

        // phase 3: stage-2 real FFT per (b, g) column, u/(u+4) radix-2 pairing
        {
            int bloc = t / 40, g = t - bloc*40;
            int b = bg*8 + bloc;
            const float4* col4 = (const float4*)(Hs + (bloc*40 + g)*22);
            float2 hc[20];
            #pragma unroll
            for (int k = 0; k < 10; k++) {
                float4 v = col4[k];
                hc[2*k]   = make_float2(v.x, v.y);
                hc[2*k+1] = make_float2(v.z, v.w);
            }
            hc[0].x *= 0.5f; hc[0].y *= 0.5f;
            float* op = out + (size_t)zo*64000 + b*1600 + g;
            #pragma unroll
            for (int u = 0; u < 4; u++) {
                float2 B0[5], B1[5];
                #pragma unroll
                for (int r = 0; r < 5; r++) {
                    float2 h2 = hc[10 + r];
                    float2 t2;
                    if      (u == 0) t2 = h2;
                    else if (u == 1) t2 = cmuli(h2);
                    else if (u == 2) t2 = make_float2(-h2.x, -h2.y);
                    else             t2 = cmulni(h2);
                    float2 P = cadd(hc[r], t2);
                    float2 Q = cadd(cmulc(hc[5 + r],  W8C[u],       W8S[u]),
                                    cmulc(hc[15 + r], W8C[(3*u)&7], W8S[(3*u)&7]));
                    float2 Au = cadd(P, Q);
                    float2 Av = csub(P, Q);
                    B0[r] = cmulc(Au, TWC[(r*u)%40],     TWS[(r*u)%40]);
                    B1[r] = cmulc(Av, TWC[(r*(u+4))%40], TWS[(r*(u+4))%40]);
                }
                #pragma unroll
                for (int s = 0; s < 5; s++) {
                    float v0 = B0[0].x, v1 = B1[0].x;
                    #pragma unroll
                    for (int r = 1; r < 5; r++) {
                        v0 += B0[r].x * TWC[(8*r*s)%40] - B0[r].y * TWS[(8*r*s)%40];
                        v1 += B1[r].x * TWC[(8*r*s)%40] - B1[r].y * TWS[(8*r*s)%40];
                    }
                    op[(8*s + u    ) * 40] = 2.0f*v0 + bv;
                    op[(8*s + u + 4) * 40] = 2.0f*v1 + bv;
                }
            }
        }
        __syncthreads();
    }
}

// ---------- launch ----------
extern "C" void kernel_launch(void* const* d_in, const int* in_sizes, int n_in,
                              void* d_out, int out_size) {
    const float* x    = (const float*)d_in[0];
    const float* kern = (const float*)d_in[1];
    const float* bias = (const float*)d_in[2];
    float* out = (float*)d_out;

    cudaFuncSetAttribute(k_zl, cudaFuncAttributeMaxDynamicSharedMemorySize, 108800);
    cudaFuncSetAttribute(k_ho, cudaFuncAttributeMaxDynamicSharedMemorySize, 112640);

    k_init<<<193, 128>>>();
    k_dft<<<dim3(8, 256), 160>>>(x);
    k_xl2cy<<<dim3(45, 16), 512>>>(kern);
    k_zl <<<dim3(32, 16), 512, 108800>>>();
    k_ho <<<dim3(256, 5), 320, 112640>>>(bias, out);
}

// round 16
// speedup vs baseline: 1.0507x; 1.0507x over previous
#include <cuda_runtime.h>
#include <math.h>
#include <stdint.h>

#define PI_D 3.14159265358979323846

// B_IN=64, B_OUT=20, B_INV=20, BATCH=16, F_IN=16, F_OUT=32, N_GRID=24
// half-pair count: sum_l (l+1)(2l+1) = 5530

__constant__ int c_hoff[20]  = {0,1,7,22,50,95,161,252,372,525,715,946,1222,1547,1925,2360,2856,3417,4047,4750};
__constant__ int c_hstep[20] = {1,6,15,28,45,66,91,120,153,190,231,276,325,378,435,496,561,630,703,780};

__device__ float  g_ws2[128*400];      // [beta_b][lm]  lm = l*l + (m+l)
__device__ float2 g_cFk[24*400];       // conj(F_k) [p][lm]
__device__ float4 g_dhA[5*5530];       // (2l+1)*d, betas bg*8+0..3, [bg][hpair]
__device__ float4 g_dhB[5*5530];       // betas bg*8+4..7
__device__ unsigned int g_pinfo[5530]; // (l<<12)|(m<<6)|ni
__device__ float2 g_tw[128*20];        // [a][m] e^{-2pi i a m/128}
__device__ float2 g_Xf[20*128*256];    // [m][b][zi]
__device__ float2 g_xl[16*400*16];     // [z][lm][i]
__device__ float2 g_cy[32*400*16];     // [o][lm][i]
__device__ float2 g_zl[512*5530];      // [zo][hpair]

// e^{+2pi i k/40} tables (static-index use only -> folded to immediates)
__device__ static constexpr float TWC[40] = {
 1.0f, 0.98768834f, 0.95105652f, 0.89100652f, 0.80901699f, 0.70710678f,
 0.58778525f, 0.45399050f, 0.30901699f, 0.15643447f, 0.0f, -0.15643447f,
 -0.30901699f, -0.45399050f, -0.58778525f, -0.70710678f, -0.80901699f,
 -0.89100652f, -0.95105652f, -0.98768834f, -1.0f, -0.98768834f, -0.95105652f,
 -0.89100652f, -0.80901699f, -0.70710678f, -0.58778525f, -0.45399050f,
 -0.30901699f, -0.15643447f, 0.0f, 0.15643447f, 0.30901699f, 0.45399050f,
 0.58778525f, 0.70710678f, 0.80901699f, 0.89100652f, 0.95105652f, 0.98768834f };
__device__ static constexpr float TWS[40] = {
 0.0f, 0.15643447f, 0.30901699f, 0.45399050f, 0.58778525f, 0.70710678f,
 0.80901699f, 0.89100652f, 0.95105652f, 0.98768834f, 1.0f, 0.98768834f,
 0.95105652f, 0.89100652f, 0.80901699f, 0.70710678f, 0.58778525f,
 0.45399050f, 0.30901699f, 0.15643447f, 0.0f, -0.15643447f, -0.30901699f,
 -0.45399050f, -0.58778525f, -0.70710678f, -0.80901699f, -0.89100652f,
 -0.95105652f, -0.98768834f, -1.0f, -0.98768834f, -0.95105652f, -0.89100652f,
 -0.80901699f, -0.70710678f, -0.58778525f, -0.45399050f, -0.30901699f,
 -0.15643447f };
// e^{+2pi i k/8}
__device__ static constexpr float W8C[8] = {1.f,0.70710678f,0.f,-0.70710678f,-1.f,-0.70710678f,0.f,0.70710678f};
__device__ static constexpr float W8S[8] = {0.f,0.70710678f,1.f,0.70710678f,0.f,-0.70710678f,-1.f,-0.70710678f};

__device__ __forceinline__ float2 cadd(float2 a, float2 b){ return make_float2(a.x+b.x, a.y+b.y); }
__device__ __forceinline__ float2 csub(float2 a, float2 b){ return make_float2(a.x-b.x, a.y-b.y); }
__device__ __forceinline__ float2 cmuli(float2 a){ return make_float2(-a.y, a.x); }      // *i
__device__ __forceinline__ float2 cmulni(float2 a){ return make_float2(a.y, -a.x); }     // *(-i)
__device__ __forceinline__ float2 cmulc(float2 a, float c, float s){                     // *(c+is)
    return make_float2(a.x*c - a.y*s, a.x*s + a.y*c);
}

// store one (beta, hpair) value into the split coalesced d-tables
__device__ __forceinline__ void store_d(int b, int hidx, float v) {
    int bb = b & 7, bgi = b >> 3;
    if (bb < 4) ((float*)&g_dhA[bgi*5530 + hidx])[bb] = v;
    else        ((float*)&g_dhB[bgi*5530 + hidx])[bb - 4] = v;
}

// ---------- fp32 Wigner-d: log-space seed + upward 3-term recurrence ----------
__device__ __forceinline__ float wseed(int m, int n, float lcb, float lsb, const float* lf) {
    int am = m < 0 ? -m : m, an = n < 0 ? -n : n;
    int l = am > an ? am : an;
    float v;
    if (am >= an) {
        float lc = 0.5f*(lf[2*l] - lf[l+n] - lf[l-n]);
        if (m >= 0) { v = expf(lc + (l+n)*lcb + (l-n)*lsb); if ((l-n)&1) v = -v; }
        else        { v = expf(lc + (l-n)*lcb + (l+n)*lsb); }
    } else {
        float lc = 0.5f*(lf[2*l] - lf[l+m] - lf[l-m]);
        if (n >= 0) { v = expf(lc + (l+m)*lcb + (l-m)*lsb); }
        else        { v = expf(lc + (l-m)*lcb + (l+m)*lsb); if ((l+m)&1) v = -v; }
    }
    return v;
}

// ---------- combined init kernel ----------
__global__ void k_init() {
    __shared__ float lf[41];
    __shared__ double sterm[64];
    __shared__ double swq;
    int t = threadIdx.x;
    if (t <= 40) lf[t] = lgammaf((float)(t + 1));
    int blk = blockIdx.x;

    if (blk < 128) {
        int b = blk;
        double beta = PI_D * (2.0*b + 1.0) / 256.0;
        if (t < 64) sterm[t] = sin((2.0*t + 1.0) * beta) / (2.0*t + 1.0);
        __syncthreads();
        if (t == 0) {
            double acc = 0.0;
            for (int k = 0; k < 64; k++) acc += sterm[k];
            swq = (2.0/64.0) * sin(beta) * acc;
        }
        __syncthreads();
        float w = (float)swq;
        float cb = (float)cos(beta*0.5), sb = (float)sin(beta*0.5);
        float cosb = (float)cos(beta);
        float lcb = logf(cb), lsb = logf(sb);
        if (t < 39) {
            int m = t - 19;
            int am = m < 0 ? -m : m;
            int l0 = am;
            float d1 = wseed(m, 0, lcb, lsb, lf), d2 = 0.0f;
            g_ws2[b*400 + l0*l0 + l0 + m] = d1 * w;
            int jstart = l0 + 1;
            if (l0 == 0) {
                d2 = d1; d1 = cosb;
                g_ws2[b*400 + 2] = d1 * w;
                jstart = 2;
            }
            for (int j = jstart; j <= 19; j++) {
                float wj  = sqrtf((float)((j*j - m*m) * (j*j)));
                float wj1 = sqrtf((float)(((j-1)*(j-1) - m*m) * ((j-1)*(j-1))));
                float d = ((2*j-1)*((float)(j*(j-1))*cosb) * d1 - (float)j*wj1*d2) / ((float)(j-1)*wj);
                g_ws2[b*400 + j*j + j + m] = d * w;
                d2 = d1; d1 = d;
            }
        }
    } else if (blk < 152) {
        int p = blk - 128;
        __syncthreads();
        double beta  = ((p >> 3) + 1) * PI_D / 24.0;
        float cb = (float)cos(beta*0.5), sb = (float)sin(beta*0.5);
        float cosb = (float)cos(beta);
        float lcb = logf(cb), lsb = logf(sb);
        if (t < 39) {
            int m = t - 19;
            int am = m < 0 ? -m : m;
            int l0 = am;
            float cph, sph;
            sincospif((float)(m * (p & 7)) * 0.25f, &sph, &cph);
            float d1 = wseed(m, 0, lcb, lsb, lf), d2 = 0.0f;
            g_cFk[p*400 + l0*l0 + l0 + m] = make_float2(d1*cph, d1*sph);
            int jstart = l0 + 1;
            if (l0 == 0) {
                d2 = d1; d1 = cosb;
                g_cFk[p*400 + 2] = make_float2(d1*cph, d1*sph);
                jstart = 2;
            }
            for (int j = jstart; j <= 19; j++) {
                float wj  = sqrtf((float)((j*j - m*m) * (j*j)));
                float wj1 = sqrtf((float)(((j-1)*(j-1) - m*m) * ((j-1)*(j-1))));
                float d = ((2*j-1)*((float)(j*(j-1))*cosb) * d1 - (float)j*wj1*d2) / ((float)(j-1)*wj);
                g_cFk[p*400 + j*j + j + m] = make_float2(d*cph, d*sph);
                d2 = d1; d1 = d;
            }
        }
    } else if (blk < 192) {
        int b = blk - 152;
        __syncthreads();
        double beta = PI_D * (2.0*b + 1.0) / 80.0;
        float cb = (float)cos(beta*0.5), sb = (float)sin(beta*0.5);
        float cosb = (float)cos(beta);
        float lcb = logf(cb), lsb = logf(sb);
        for (int p = t; p < 780; p += blockDim.x) {
            int m = p / 39, nj = p % 39, n = nj - 19;
            int an = n < 0 ? -n : n;
            int l0 = m > an ? m : an;
            float d1 = wseed(m, n, lcb, lsb, lf), d2 = 0.0f;
            store_d(b, c_hoff[l0] + m*(2*l0+1) + n + l0, (float)(2*l0+1) * d1);
            int jstart = l0 + 1;
            if (l0 == 0) {
                d2 = d1; d1 = cosb;
                store_d(b, c_hoff[1] + 1, 3.0f * d1);
                jstart = 2;
            }
            float mn = (float)(m * n);
            for (int j = jstart; j <= 19; j++) {
                float wj  = sqrtf((float)((j*j - m*m) * (j*j - n*n)));
                float wj1 = sqrtf((float)(((j-1)*(j-1) - m*m) * ((j-1)*(j-1) - n*n)));
                float d = ((2*j-1)*((float)(j*(j-1))*cosb - mn) * d1 - (float)j*wj1*d2) / ((float)(j-1)*wj);
                store_d(b, c_hoff[j] + m*(2*j+1) + n + j, (float)(2*j+1) * d);
                d2 = d1; d1 = d;
            }
        }
    } else {
        __syncthreads();
        for (int p = t; p < 5530; p += blockDim.x) {
            int l = 0, acc = 0;
            for (; l < 20; l++) {
                int sz = (l+1)*(2*l+1);
                if (p < acc + sz) break;
                acc += sz;
            }
            int r = p - acc, w = 2*l + 1;
            g_pinfo[p] = (unsigned)((l << 12) | ((r / w) << 6) | (r % w));
        }
        for (int idx = t; idx < 2560; idx += blockDim.x) {
            int a = idx / 20, m = idx % 20;
            float s, c;
            sincospif(-(float)(a * m) / 64.0f, &s, &c);
            g_tw[idx] = make_float2(c, s);
        }
    }
}

// ---------- K1: truncated real DFT over alpha via twiddle table ----------
__global__ void k_dft(const float* __restrict__ x) {
    __shared__ float  xs[16][130];
    __shared__ float2 tws[128*20];
    int bg = blockIdx.x, zi = blockIdx.y;
    const float* xp = x + (zi * 128 + bg * 16) * 128;
    for (int idx = threadIdx.x; idx < 2048; idx += 160)
        xs[idx >> 7][idx & 127] = xp[idx];
    for (int idx = threadIdx.x; idx < 2560; idx += 160)
        tws[idx] = g_tw[idx];
    __syncthreads();
    int bp = threadIdx.x / 20;
    int m  = threadIdx.x % 20;
    const float* r0 = xs[2*bp];
    const float* r1 = xs[2*bp + 1];
    float a0r = 0.f, a0i = 0.f, a1r = 0.f, a1i = 0.f;
    #pragma unroll 4
    for (int a = 0; a < 128; a++) {
        float2 w = tws[a*20 + m];
        float x0 = r0[a], x1 = r1[a];
        a0r += x0*w.x; a0i += x0*w.y;
        a1r += x1*w.x; a1i += x1*w.y;
    }
    int b = bg * 16 + 2*bp;
    g_Xf[(m*128 + b    )*256 + zi] = make_float2(a0r, a0i);
    g_Xf[(m*128 + b + 1)*256 + zi] = make_float2(a1r, a1i);
}

// ---------- K2: S2 analysis tiled by (|m|, z), with k_cy work fused as extra blocks ----------
__global__ void k_xl2cy(const float* __restrict__ kern) {
    __shared__ float2 Xs[128*16];
    __shared__ float wsp[128*20];
    __shared__ float wsm[128*20];
    __shared__ float2 sF[24];
    int t = threadIdx.x;
    if (blockIdx.x >= 20) {
        // ---- cy path ----
        int lm = (blockIdx.x - 20) * 16 + blockIdx.y;
        if (t < 24) sF[t] = g_cFk[t * 400 + lm];
        __syncthreads();
        int i = t >> 5, o = t & 31;
        const float* kp = kern + (i * 32 + o) * 24;
        float ar = 0.0f, ai = 0.0f;
        for (int p = 0; p < 24; p++) {
            float k = kp[p];
            ar += k * sF[p].x; ai += k * sF[p].y;
        }
        const float S = 0.00816496580927726f;
        g_cy[((size_t)o * 400 + lm) * 16 + i] = make_float2(ar * S, ai * S);
        return;
    }
    // ---- xl2 path ----
    int ma = blockIdx.x, z = blockIdx.y;
    int nl = 20 - ma;
    for (int idx = t; idx < 2048; idx += 512) {
        int b = idx >> 4, i = idx & 15;
        Xs[idx] = g_Xf[(ma*128 + b)*256 + z*16 + i];
    }
    for (int idx = t; idx < 128*nl; idx += 512) {
        int b = idx / nl, li = idx % nl;
        int l = ma + li;
        wsp[idx] = g_ws2[b*400 + l*l + l + ma];
        if (ma > 0) wsm[idx] = g_ws2[b*400 + l*l + l - ma];
    }
    __syncthreads();
    for (int item = t; item < nl*16; item += 512) {
        int li = item >> 4, i = item & 15;
        int l = ma + li;
        float pr = 0.f, pi = 0.f, mr = 0.f, mi = 0.f;
        for (int b = 0; b < 128; b++) {
            float2 xv = Xs[b*16 + i];
            float wp = wsp[b*nl + li];
            pr += wp * xv.x; pi += wp * xv.y;
            if (ma > 0) {
                float wm = wsm[b*nl + li];
                mr += wm * xv.x; mi -= wm * xv.y;
            }
        }
        g_xl[((size_t)z*400 + l*l + l + ma)*16 + i] = make_float2(pr, pi);
        if (ma > 0)
            g_xl[((size_t)z*400 + l*l + l - ma)*16 + i] = make_float2(mr, mi);
    }
}

// ---------- K4: zl[zo][hpair], LDS.128, BOTH tiles padded to pitch 18 (bank spread) ----------
__global__ void k_zl() {
    extern __shared__ float2 sm4[];
    float2* xs = sm4;            // [lm][i] pitch 18 (16B-aligned, banks spread by 4*lm)
    float2* cs = sm4 + 7200;     // [lm][i] pitch 18
    int o = blockIdx.x, z = blockIdx.y;
    for (int idx = threadIdx.x; idx < 6400; idx += blockDim.x) {
        int lm = idx >> 4, i = idx & 15;
        xs[lm * 18 + i] = g_xl[(size_t)z * 6400 + idx];
        cs[lm * 18 + i] = g_cy[(size_t)o * 6400 + idx];
    }
    __syncthreads();
    float2* outp = g_zl + (size_t)(z * 32 + o) * 5530;
    for (int p = threadIdx.x; p < 5530; p += blockDim.x) {
        unsigned info = g_pinfo[p];
        int l = info >> 12, m = (info >> 6) & 63, ni = info & 63;
        const float4* A4 = (const float4*)(xs + (l*l + l + m) * 18);
        const float4* B4 = (const float4*)(cs + (l*l + ni) * 18);
        float ar = 0.0f, ai = 0.0f;
        #pragma unroll
        for (int i = 0; i < 8; i++) {
            float4 a = A4[i], c = B4[i];
            ar += a.x*c.x - a.y*c.y;
            ai += a.x*c.y + a.y*c.x;
            ar += a.z*c.z - a.w*c.w;
            ai += a.z*c.w + a.w*c.z;
        }
        outp[p] = make_float2(ar, ai);
    }
}

// ---------- stage1 40-pt FFT partials: T[r][up] for u = 4*HH+up ----------
template<int HH>
__device__ __forceinline__ void fft40_T(const float2* __restrict__ Grow, float2 T[5][4]) {
    const float R2 = 0.70710678f;
    #pragma unroll
    for (int r = 0; r < 5; r++) {
        float2 x0=Grow[r],    x1=Grow[5+r],  x2=Grow[10+r], x3=Grow[15+r];
        float2 x4=Grow[20+r], x5=Grow[25+r], x6=Grow[30+r], x7=Grow[35+r];
        float2 a04=cadd(x0,x4), s04=csub(x0,x4);
        float2 a26=cadd(x2,x6), s26=csub(x2,x6);
        float2 E0=cadd(a04,a26), E1=cadd(s04,cmuli(s26));
        float2 E2=csub(a04,a26), E3=csub(s04,cmuli(s26));
        float2 a15=cadd(x1,x5), s15=csub(x1,x5);
        float2 a37=cadd(x3,x7), s37=csub(x3,x7);
        float2 O0=cadd(a15,a37), O1=cadd(s15,cmuli(s37));
        float2 O2=csub(a15,a37), O3=csub(s15,cmuli(s37));
        float2 w1o = make_float2(R2*(O1.x-O1.y), R2*(O1.x+O1.y));  // W8^1 * O1
        float2 w2o = cmuli(O2);                                     // W8^2 * O2
        float2 w3o = make_float2(-R2*(O3.x+O3.y), R2*(O3.x-O3.y)); // W8^3 * O3
        float2 y0, y1, y2, y3;
        if (HH == 0) { y0=cadd(E0,O0); y1=cadd(E1,w1o); y2=cadd(E2,w2o); y3=cadd(E3,w3o); }
        else         { y0=csub(E0,O0); y1=csub(E1,w1o); y2=csub(E2,w2o); y3=csub(E3,w3o); }
        T[r][0] = cmulc(y0, TWC[(r*(4*HH+0))%40], TWS[(r*(4*HH+0))%40]);
        T[r][1] = cmulc(y1, TWC[(r*(4*HH+1))%40], TWS[(r*(4*HH+1))%40]);
        T[r][2] = cmulc(y2, TWC[(r*(4*HH+2))%40], TWS[(r*(4*HH+2))%40]);
        T[r][3] = cmulc(y3, TWC[(r*(4*HH+3))%40], TWS[(r*(4*HH+3))%40]);
    }
}

// ---------- K5 fused: register-blocked G-build + stage1 FFT + stage2 + output ----------
// (reverted to the proven R14 single-zo form; H pitch 22)
__global__ void __launch_bounds__(320, 2) k_ho(const float* __restrict__ bias,
                                               float* __restrict__ out) {
    extern __shared__ float2 sm5[];
    float2* Gs = sm5;
    float2* Hs = sm5;
    int zo = blockIdx.x, bg = blockIdx.y;
    int t = threadIdx.x;

    // phase 1: build G for 8 betas at once (register-blocked over beta, coalesced d)
    const float2* zrow = g_zl + (size_t)zo * 5530;
    const float4* dA = g_dhA + bg * 5530;
    const float4* dB = g_dhB + bg * 5530;
    for (int e = t; e < 800; e += 320) {
        int m = e / 40, j = e % 40;
        int n = (j <= 19) ? j : j - 40;
        int an = n < 0 ? -n : n;
        int lmin = m > an ? m : an;
        int idx = c_hoff[lmin] + m*(2*lmin + 1) + (n + lmin);
        int inc = 2*m + 1;
        float gr0=0.f,gi0=0.f,gr1=0.f,gi1=0.f,gr2=0.f,gi2=0.f,gr3=0.f,gi3=0.f;
        float gr4=0.f,gi4=0.f,gr5=0.f,gi5=0.f,gr6=0.f,gi6=0.f,gr7=0.f,gi7=0.f;
        #pragma unroll 2
        for (int l = lmin; l < 20; l++) {
            float2 zv = __ldg(zrow + idx);
            float4 d0 = __ldg(dA + idx);
            float4 d1 = __ldg(dB + idx);
            gr0 += zv.x*d0.x; gi0 += zv.y*d0.x;
            gr1 += zv.x*d0.y; gi1 += zv.y*d0.y;
            gr2 += zv.x*d0.z; gi2 += zv.y*d0.z;
            gr3 += zv.x*d0.w; gi3 += zv.y*d0.w;
            gr4 += zv.x*d1.x; gi4 += zv.y*d1.x;
            gr5 += zv.x*d1.y; gi5 += zv.y*d1.y;
            gr6 += zv.x*d1.z; gi6 += zv.y*d1.z;
            gr7 += zv.x*d1.w; gi7 += zv.y*d1.w;
            idx += c_hstep[l] + inc;
        }
        int base = m*41 + j;
        Gs[base        ] = make_float2(gr0, gi0);
        Gs[base +  820 ] = make_float2(gr1, gi1);
        Gs[base + 1640 ] = make_float2(gr2, gi2);
        Gs[base + 2460 ] = make_float2(gr3, gi3);
        Gs[base + 3280 ] = make_float2(gr4, gi4);
        Gs[base + 4100 ] = make_float2(gr5, gi5);
        Gs[base + 4920 ] = make_float2(gr6, gi6);
        Gs[base + 5740 ] = make_float2(gr7, gi7);
    }
    __syncthreads();

    // phase 2a: stage-1 FFT partials in registers (reads Gs only)
    int h = t / 160, row = t - h*160;
    int blocR = row / 20, mR = row % 20;
    float2 T[5][4];
    {
        const float2* Grow = Gs + row*41;
        if (h == 0) fft40_T<0>(Grow, T);
        else        fft40_T<1>(Grow, T);
    }
    __syncthreads();   // all Gs reads done; region becomes H

    // phase 2b: combine + write H into smem (pitch 22)
    {
        float2* dsts = Hs + blocR*880 + mR;   // + (8s+u)*22
        #pragma unroll
        for (int up = 0; up < 4; up++) {
            int u = 4*h + up;
            #pragma unroll
            for (int s = 0; s < 5; s++) {
                float2 acc = T[0][up];
                #pragma unroll
                for (int r = 1; r < 5; r++)
                    acc = cadd(acc, cmulc(T[r][up], TWC[(8*r*s)%40], TWS[(8*r*s)%40]));
                dsts[(8*s + u) * 22] = acc;
            }
        }
    }
    __syncthreads();

    // phase 3: stage-2 real FFT per (b, g) column, u/(u+4) radix-2 pairing
    {
        int bloc = t / 40, g = t - bloc*40;
        int b = bg*8 + bloc;
        const float4* col4 = (const float4*)(Hs + (bloc*40 + g)*22);
        float2 hc[20];
        #pragma unroll
        for (int k = 0; k < 10; k++) {
            float4 v = col4[k];
            hc[2*k]   = make_float2(v.x, v.y);
            hc[2*k+1] = make_float2(v.z, v.w);
        }
        hc[0].x *= 0.5f; hc[0].y *= 0.5f;
        float bv = bias[zo & 31];
        float* op = out + (size_t)zo*64000 + b*1600 + g;
        #pragma unroll
        for (int u = 0; u < 4; u++) {
            float2 B0[5], B1[5];
            #pragma unroll
            for (int r = 0; r < 5; r++) {
                float2 h2 = hc[10 + r];
                float2 t2;
                if      (u == 0) t2 = h2;
                else if (u == 1) t2 = cmuli(h2);
                else if (u == 2) t2 = make_float2(-h2.x, -h2.y);
                else             t2 = cmulni(h2);
                float2 P = cadd(hc[r], t2);
                float2 Q = cadd(cmulc(hc[5 + r],  W8C[u],       W8S[u]),
                                cmulc(hc[15 + r], W8C[(3*u)&7], W8S[(3*u)&7]));
                float2 Au = cadd(P, Q);
                float2 Av = csub(P, Q);
                B0[r] = cmulc(Au, TWC[(r*u)%40],     TWS[(r*u)%40]);
                B1[r] = cmulc(Av, TWC[(r*(u+4))%40], TWS[(r*(u+4))%40]);
            }
            #pragma unroll
            for (int s = 0; s < 5; s++) {
                float v0 = B0[0].x, v1 = B1[0].x;
                #pragma unroll
                for (int r = 1; r < 5; r++) {
                    v0 += B0[r].x * TWC[(8*r*s)%40] - B0[r].y * TWS[(8*r*s)%40];
                    v1 += B1[r].x * TWC[(8*r*s)%40] - B1[r].y * TWS[(8*r*s)%40];
                }
                op[(8*s + u    ) * 40] = 2.0f*v0 + bv;
                op[(8*s + u + 4) * 40] = 2.0f*v1 + bv;
            }
        }
    }
}

// ---------- launch ----------
extern "C" void kernel_launch(void* const* d_in, const int* in_sizes, int n_in,
                              void* d_out, int out_size) {
    const float* x    = (const float*)d_in[0];
    const float* kern = (const float*)d_in[1];
    const float* bias = (const float*)d_in[2];
    float* out = (float*)d_out;

    cudaFuncSetAttribute(k_zl, cudaFuncAttributeMaxDynamicSharedMemorySize, 115200);
    cudaFuncSetAttribute(k_ho, cudaFuncAttributeMaxDynamicSharedMemorySize, 56320);

    k_init<<<193, 128>>>();
    k_dft<<<dim3(8, 256), 160>>>(x);
    k_xl2cy<<<dim3(45, 16), 512>>>(kern);
    k_zl <<<dim3(32, 16), 512, 115200>>>();
    k_ho <<<dim3(512, 5), 320, 56320>>>(bias, out);
}

// round 17
// speedup vs baseline: 1.0838x; 1.0315x over previous
#include <cuda_runtime.h>
#include <math.h>
#include <stdint.h>

#define PI_D 3.14159265358979323846

// B_IN=64, B_OUT=20, B_INV=20, BATCH=16, F_IN=16, F_OUT=32, N_GRID=24
// half-pair count: sum_l (l+1)(2l+1) = 5530

__constant__ int c_hoff[20]  = {0,1,7,22,50,95,161,252,372,525,715,946,1222,1547,1925,2360,2856,3417,4047,4750};
__constant__ int c_hstep[20] = {1,6,15,28,45,66,91,120,153,190,231,276,325,378,435,496,561,630,703,780};

__device__ float  g_ws2[128*400];      // [beta_b][lm]  lm = l*l + (m+l)
__device__ float2 g_cFk[24*400];       // conj(F_k) [p][lm]
__device__ float4 g_dhA[5*5530];       // (2l+1)*d, betas bg*8+0..3, [bg][hpair]
__device__ float4 g_dhB[5*5530];       // betas bg*8+4..7
__device__ unsigned int g_pinfo[5530]; // (l<<12)|(m<<6)|ni
__device__ float2 g_tw[128*20];        // [a][m] e^{-2pi i a m/128}
__device__ float2 g_Xf[20*128*256];    // [m][b][zi]
__device__ float2 g_xl[16*400*16];     // [z][lm][i]
__device__ float2 g_cy[32*400*16];     // [o][lm][i]
__device__ float2 g_zl[512*5530];      // [zo][hpair]

// e^{+2pi i k/40} tables (static-index use only -> folded to immediates)
__device__ static constexpr float TWC[40] = {
 1.0f, 0.98768834f, 0.95105652f, 0.89100652f, 0.80901699f, 0.70710678f,
 0.58778525f, 0.45399050f, 0.30901699f, 0.15643447f, 0.0f, -0.15643447f,
 -0.30901699f, -0.45399050f, -0.58778525f, -0.70710678f, -0.80901699f,
 -0.89100652f, -0.95105652f, -0.98768834f, -1.0f, -0.98768834f, -0.95105652f,
 -0.89100652f, -0.80901699f, -0.70710678f, -0.58778525f, -0.45399050f,
 -0.30901699f, -0.15643447f, 0.0f, 0.15643447f, 0.30901699f, 0.45399050f,
 0.58778525f, 0.70710678f, 0.80901699f, 0.89100652f, 0.95105652f, 0.98768834f };
__device__ static constexpr float TWS[40] = {
 0.0f, 0.15643447f, 0.30901699f, 0.45399050f, 0.58778525f, 0.70710678f,
 0.80901699f, 0.89100652f, 0.95105652f, 0.98768834f, 1.0f, 0.98768834f,
 0.95105652f, 0.89100652f, 0.80901699f, 0.70710678f, 0.58778525f,
 0.45399050f, 0.30901699f, 0.15643447f, 0.0f, -0.15643447f, -0.30901699f,
 -0.45399050f, -0.58778525f, -0.70710678f, -0.80901699f, -0.89100652f,
 -0.95105652f, -0.98768834f, -1.0f, -0.98768834f, -0.95105652f, -0.89100652f,
 -0.80901699f, -0.70710678f, -0.58778525f, -0.45399050f, -0.30901699f,
 -0.15643447f };
// e^{+2pi i k/8}
__device__ static constexpr float W8C[8] = {1.f,0.70710678f,0.f,-0.70710678f,-1.f,-0.70710678f,0.f,0.70710678f};
__device__ static constexpr float W8S[8] = {0.f,0.70710678f,1.f,0.70710678f,0.f,-0.70710678f,-1.f,-0.70710678f};

__device__ __forceinline__ float2 cadd(float2 a, float2 b){ return make_float2(a.x+b.x, a.y+b.y); }
__device__ __forceinline__ float2 csub(float2 a, float2 b){ return make_float2(a.x-b.x, a.y-b.y); }
__device__ __forceinline__ float2 cmuli(float2 a){ return make_float2(-a.y, a.x); }      // *i
__device__ __forceinline__ float2 cmulni(float2 a){ return make_float2(a.y, -a.x); }     // *(-i)
__device__ __forceinline__ float2 cmulc(float2 a, float c, float s){                     // *(c+is)
    return make_float2(a.x*c - a.y*s, a.x*s + a.y*c);
}

// store one (beta, hpair) value into the split coalesced d-tables
__device__ __forceinline__ void store_d(int b, int hidx, float v) {
    int bb = b & 7, bgi = b >> 3;
    if (bb < 4) ((float*)&g_dhA[bgi*5530 + hidx])[bb] = v;
    else        ((float*)&g_dhB[bgi*5530 + hidx])[bb - 4] = v;
}

// ---------- fp32 Wigner-d: log-space seed + upward 3-term recurrence ----------
__device__ __forceinline__ float wseed(int m, int n, float lcb, float lsb, const float* lf) {
    int am = m < 0 ? -m : m, an = n < 0 ? -n : n;
    int l = am > an ? am : an;
    float v;
    if (am >= an) {
        float lc = 0.5f*(lf[2*l] - lf[l+n] - lf[l-n]);
        if (m >= 0) { v = expf(lc + (l+n)*lcb + (l-n)*lsb); if ((l-n)&1) v = -v; }
        else        { v = expf(lc + (l-n)*lcb + (l+n)*lsb); }
    } else {
        float lc = 0.5f*(lf[2*l] - lf[l+m] - lf[l-m]);
        if (n >= 0) { v = expf(lc + (l+m)*lcb + (l-m)*lsb); }
        else        { v = expf(lc + (l-m)*lcb + (l+m)*lsb); if ((l+m)&1) v = -v; }
    }
    return v;
}

// ---------- combined init kernel ----------
__global__ void k_init() {
    __shared__ float lf[41];
    __shared__ double sterm[64];
    __shared__ double swq;
    int t = threadIdx.x;
    if (t <= 40) lf[t] = lgammaf((float)(t + 1));
    int blk = blockIdx.x;

    if (blk < 128) {
        int b = blk;
        double beta = PI_D * (2.0*b + 1.0) / 256.0;
        if (t < 64) sterm[t] = sin((2.0*t + 1.0) * beta) / (2.0*t + 1.0);
        __syncthreads();
        if (t == 0) {
            double acc = 0.0;
            for (int k = 0; k < 64; k++) acc += sterm[k];
            swq = (2.0/64.0) * sin(beta) * acc;
        }
        __syncthreads();
        float w = (float)swq;
        float cb = (float)cos(beta*0.5), sb = (float)sin(beta*0.5);
        float cosb = (float)cos(beta);
        float lcb = logf(cb), lsb = logf(sb);
        if (t < 39) {
            int m = t - 19;
            int am = m < 0 ? -m : m;
            int l0 = am;
            float d1 = wseed(m, 0, lcb, lsb, lf), d2 = 0.0f;
            g_ws2[b*400 + l0*l0 + l0 + m] = d1 * w;
            int jstart = l0 + 1;
            if (l0 == 0) {
                d2 = d1; d1 = cosb;
                g_ws2[b*400 + 2] = d1 * w;
                jstart = 2;
            }
            for (int j = jstart; j <= 19; j++) {
                float wj  = sqrtf((float)((j*j - m*m) * (j*j)));
                float wj1 = sqrtf((float)(((j-1)*(j-1) - m*m) * ((j-1)*(j-1))));
                float d = ((2*j-1)*((float)(j*(j-1))*cosb) * d1 - (float)j*wj1*d2) / ((float)(j-1)*wj);
                g_ws2[b*400 + j*j + j + m] = d * w;
                d2 = d1; d1 = d;
            }
        }
    } else if (blk < 152) {
        int p = blk - 128;
        __syncthreads();
        double beta  = ((p >> 3) + 1) * PI_D / 24.0;
        float cb = (float)cos(beta*0.5), sb = (float)sin(beta*0.5);
        float cosb = (float)cos(beta);
        float lcb = logf(cb), lsb = logf(sb);
        if (t < 39) {
            int m = t - 19;
            int am = m < 0 ? -m : m;
            int l0 = am;
            float cph, sph;
            sincospif((float)(m * (p & 7)) * 0.25f, &sph, &cph);
            float d1 = wseed(m, 0, lcb, lsb, lf), d2 = 0.0f;
            g_cFk[p*400 + l0*l0 + l0 + m] = make_float2(d1*cph, d1*sph);
            int jstart = l0 + 1;
            if (l0 == 0) {
                d2 = d1; d1 = cosb;
                g_cFk[p*400 + 2] = make_float2(d1*cph, d1*sph);
                jstart = 2;
            }
            for (int j = jstart; j <= 19; j++) {
                float wj  = sqrtf((float)((j*j - m*m) * (j*j)));
                float wj1 = sqrtf((float)(((j-1)*(j-1) - m*m) * ((j-1)*(j-1))));
                float d = ((2*j-1)*((float)(j*(j-1))*cosb) * d1 - (float)j*wj1*d2) / ((float)(j-1)*wj);
                g_cFk[p*400 + j*j + j + m] = make_float2(d*cph, d*sph);
                d2 = d1; d1 = d;
            }
        }
    } else if (blk < 192) {
        int b = blk - 152;
        __syncthreads();
        double beta = PI_D * (2.0*b + 1.0) / 80.0;
        float cb = (float)cos(beta*0.5), sb = (float)sin(beta*0.5);
        float cosb = (float)cos(beta);
        float lcb = logf(cb), lsb = logf(sb);
        for (int p = t; p < 780; p += blockDim.x) {
            int m = p / 39, nj = p % 39, n = nj - 19;
            int an = n < 0 ? -n : n;
            int l0 = m > an ? m : an;
            float d1 = wseed(m, n, lcb, lsb, lf), d2 = 0.0f;
            store_d(b, c_hoff[l0] + m*(2*l0+1) + n + l0, (float)(2*l0+1) * d1);
            int jstart = l0 + 1;
            if (l0 == 0) {
                d2 = d1; d1 = cosb;
                store_d(b, c_hoff[1] + 1, 3.0f * d1);
                jstart = 2;
            }
            float mn = (float)(m * n);
            for (int j = jstart; j <= 19; j++) {
                float wj  = sqrtf((float)((j*j - m*m) * (j*j - n*n)));
                float wj1 = sqrtf((float)(((j-1)*(j-1) - m*m) * ((j-1)*(j-1) - n*n)));
                float d = ((2*j-1)*((float)(j*(j-1))*cosb - mn) * d1 - (float)j*wj1*d2) / ((float)(j-1)*wj);
                store_d(b, c_hoff[j] + m*(2*j+1) + n + j, (float)(2*j+1) * d);
                d2 = d1; d1 = d;
            }
        }
    } else {
        __syncthreads();
        for (int p = t; p < 5530; p += blockDim.x) {
            int l = 0, acc = 0;
            for (; l < 20; l++) {
                int sz = (l+1)*(2*l+1);
                if (p < acc + sz) break;
                acc += sz;
            }
            int r = p - acc, w = 2*l + 1;
            g_pinfo[p] = (unsigned)((l << 12) | ((r / w) << 6) | (r % w));
        }
        for (int idx = t; idx < 2560; idx += blockDim.x) {
            int a = idx / 20, m = idx % 20;
            float s, c;
            sincospif(-(float)(a * m) / 64.0f, &s, &c);
            g_tw[idx] = make_float2(c, s);
        }
    }
}

// ---------- K1: truncated real DFT over alpha via twiddle table ----------
__global__ void k_dft(const float* __restrict__ x) {
    __shared__ float  xs[16][130];
    __shared__ float2 tws[128*20];
    int bg = blockIdx.x, zi = blockIdx.y;
    const float* xp = x + (zi * 128 + bg * 16) * 128;
    for (int idx = threadIdx.x; idx < 2048; idx += 160)
        xs[idx >> 7][idx & 127] = xp[idx];
    for (int idx = threadIdx.x; idx < 2560; idx += 160)
        tws[idx] = g_tw[idx];
    __syncthreads();
    int bp = threadIdx.x / 20;
    int m  = threadIdx.x % 20;
    const float* r0 = xs[2*bp];
    const float* r1 = xs[2*bp + 1];
    float a0r = 0.f, a0i = 0.f, a1r = 0.f, a1i = 0.f;
    #pragma unroll 4
    for (int a = 0; a < 128; a++) {
        float2 w = tws[a*20 + m];
        float x0 = r0[a], x1 = r1[a];
        a0r += x0*w.x; a0i += x0*w.y;
        a1r += x1*w.x; a1i += x1*w.y;
    }
    int b = bg * 16 + 2*bp;
    g_Xf[(m*128 + b    )*256 + zi] = make_float2(a0r, a0i);
    g_Xf[(m*128 + b + 1)*256 + zi] = make_float2(a1r, a1i);
}

// ---------- K2: S2 analysis tiled by (|m|, z), with k_cy work fused as extra blocks ----------
__global__ void k_xl2cy(const float* __restrict__ kern) {
    __shared__ float2 Xs[128*16];
    __shared__ float wsp[128*20];
    __shared__ float wsm[128*20];
    __shared__ float2 sF[24];
    int t = threadIdx.x;
    if (blockIdx.x >= 20) {
        // ---- cy path ----
        int lm = (blockIdx.x - 20) * 16 + blockIdx.y;
        if (t < 24) sF[t] = g_cFk[t * 400 + lm];
        __syncthreads();
        int i = t >> 5, o = t & 31;
        const float* kp = kern + (i * 32 + o) * 24;
        float ar = 0.0f, ai = 0.0f;
        for (int p = 0; p < 24; p++) {
            float k = kp[p];
            ar += k * sF[p].x; ai += k * sF[p].y;
        }
        const float S = 0.00816496580927726f;
        g_cy[((size_t)o * 400 + lm) * 16 + i] = make_float2(ar * S, ai * S);
        return;
    }
    // ---- xl2 path ----
    int ma = blockIdx.x, z = blockIdx.y;
    int nl = 20 - ma;
    for (int idx = t; idx < 2048; idx += 512) {
        int b = idx >> 4, i = idx & 15;
        Xs[idx] = g_Xf[(ma*128 + b)*256 + z*16 + i];
    }
    for (int idx = t; idx < 128*nl; idx += 512) {
        int b = idx / nl, li = idx % nl;
        int l = ma + li;
        wsp[idx] = g_ws2[b*400 + l*l + l + ma];
        if (ma > 0) wsm[idx] = g_ws2[b*400 + l*l + l - ma];
    }
    __syncthreads();
    for (int item = t; item < nl*16; item += 512) {
        int li = item >> 4, i = item & 15;
        int l = ma + li;
        float pr = 0.f, pi = 0.f, mr = 0.f, mi = 0.f;
        for (int b = 0; b < 128; b++) {
            float2 xv = Xs[b*16 + i];
            float wp = wsp[b*nl + li];
            pr += wp * xv.x; pi += wp * xv.y;
            if (ma > 0) {
                float wm = wsm[b*nl + li];
                mr += wm * xv.x; mi -= wm * xv.y;
            }
        }
        g_xl[((size_t)z*400 + l*l + l + ma)*16 + i] = make_float2(pr, pi);
        if (ma > 0)
            g_xl[((size_t)z*400 + l*l + l - ma)*16 + i] = make_float2(mr, mi);
    }
}

// ---------- K4: zl[zo][hpair], LDS.128, BOTH tiles padded to pitch 18 (bank spread) ----------
__global__ void k_zl() {
    extern __shared__ float2 sm4[];
    float2* xs = sm4;            // [lm][i] pitch 18 (16B-aligned, banks spread by 4*lm)
    float2* cs = sm4 + 7200;     // [lm][i] pitch 18
    int o = blockIdx.x, z = blockIdx.y;
    for (int idx = threadIdx.x; idx < 6400; idx += blockDim.x) {
        int lm = idx >> 4, i = idx & 15;
        xs[lm * 18 + i] = g_xl[(size_t)z * 6400 + idx];
        cs[lm * 18 + i] = g_cy[(size_t)o * 6400 + idx];
    }
    __syncthreads();
    float2* outp = g_zl + (size_t)(z * 32 + o) * 5530;
    for (int p = threadIdx.x; p < 5530; p += blockDim.x) {
        unsigned info = g_pinfo[p];
        int l = info >> 12, m = (info >> 6) & 63, ni = info & 63;
        const float4* A4 = (const float4*)(xs + (l*l + l + m) * 18);
        const float4* B4 = (const float4*)(cs + (l*l + ni) * 18);
        float ar = 0.0f, ai = 0.0f;
        #pragma unroll
        for (int i = 0; i < 8; i++) {
            float4 a = A4[i], c = B4[i];
            ar += a.x*c.x - a.y*c.y;
            ai += a.x*c.y + a.y*c.x;
            ar += a.z*c.z - a.w*c.w;
            ai += a.z*c.w + a.w*c.z;
        }
        outp[p] = make_float2(ar, ai);
    }
}

// ---------- stage1 40-pt FFT partials: T[r][up] for u = 4*HH+up ----------
template<int HH>
__device__ __forceinline__ void fft40_T(const float2* __restrict__ Grow, float2 T[5][4]) {
    const float R2 = 0.70710678f;
    #pragma unroll
    for (int r = 0; r < 5; r++) {
        float2 x0=Grow[r],    x1=Grow[5+r],  x2=Grow[10+r], x3=Grow[15+r];
        float2 x4=Grow[20+r], x5=Grow[25+r], x6=Grow[30+r], x7=Grow[35+r];
        float2 a04=cadd(x0,x4), s04=csub(x0,x4);
        float2 a26=cadd(x2,x6), s26=csub(x2,x6);
        float2 E0=cadd(a04,a26), E1=cadd(s04,cmuli(s26));
        float2 E2=csub(a04,a26), E3=csub(s04,cmuli(s26));
        float2 a15=cadd(x1,x5), s15=csub(x1,x5);
        float2 a37=cadd(x3,x7), s37=csub(x3,x7);
        float2 O0=cadd(a15,a37), O1=cadd(s15,cmuli(s37));
        float2 O2=csub(a15,a37), O3=csub(s15,cmuli(s37));
        float2 w1o = make_float2(R2*(O1.x-O1.y), R2*(O1.x+O1.y));  // W8^1 * O1
        float2 w2o = cmuli(O2);                                     // W8^2 * O2
        float2 w3o = make_float2(-R2*(O3.x+O3.y), R2*(O3.x-O3.y)); // W8^3 * O3
        float2 y0, y1, y2, y3;
        if (HH == 0) { y0=cadd(E0,O0); y1=cadd(E1,w1o); y2=cadd(E2,w2o); y3=cadd(E3,w3o); }
        else         { y0=csub(E0,O0); y1=csub(E1,w1o); y2=csub(E2,w2o); y3=csub(E3,w3o); }
        T[r][0] = cmulc(y0, TWC[(r*(4*HH+0))%40], TWS[(r*(4*HH+0))%40]);
        T[r][1] = cmulc(y1, TWC[(r*(4*HH+1))%40], TWS[(r*(4*HH+1))%40]);
        T[r][2] = cmulc(y2, TWC[(r*(4*HH+2))%40], TWS[(r*(4*HH+2))%40]);
        T[r][3] = cmulc(y3, TWC[(r*(4*HH+3))%40], TWS[(r*(4*HH+3))%40]);
    }
}

// ---------- K5 fused: register-blocked G-build + stage1 FFT + stage2 + output ----------
// (proven R14 single-zo form, no unroll pragma in phase 1; H pitch 22)
__global__ void __launch_bounds__(320, 2) k_ho(const float* __restrict__ bias,
                                               float* __restrict__ out) {
    extern __shared__ float2 sm5[];
    float2* Gs = sm5;
    float2* Hs = sm5;
    int zo = blockIdx.x, bg = blockIdx.y;
    int t = threadIdx.x;

    // phase 1: build G for 8 betas at once (register-blocked over beta, coalesced d)
    const float2* zrow = g_zl + (size_t)zo * 5530;
    const float4* dA = g_dhA + bg * 5530;
    const float4* dB = g_dhB + bg * 5530;
    for (int e = t; e < 800; e += 320) {
        int m = e / 40, j = e % 40;
        int n = (j <= 19) ? j : j - 40;
        int an = n < 0 ? -n : n;
        int lmin = m > an ? m : an;
        int idx = c_hoff[lmin] + m*(2*lmin + 1) + (n + lmin);
        int inc = 2*m + 1;
        float gr0=0.f,gi0=0.f,gr1=0.f,gi1=0.f,gr2=0.f,gi2=0.f,gr3=0.f,gi3=0.f;
        float gr4=0.f,gi4=0.f,gr5=0.f,gi5=0.f,gr6=0.f,gi6=0.f,gr7=0.f,gi7=0.f;
        for (int l = lmin; l < 20; l++) {
            float2 zv = __ldg(zrow + idx);
            float4 d0 = __ldg(dA + idx);
            float4 d1 = __ldg(dB + idx);
            gr0 += zv.x*d0.x; gi0 += zv.y*d0.x;
            gr1 += zv.x*d0.y; gi1 += zv.y*d0.y;
            gr2 += zv.x*d0.z; gi2 += zv.y*d0.z;
            gr3 += zv.x*d0.w; gi3 += zv.y*d0.w;
            gr4 += zv.x*d1.x; gi4 += zv.y*d1.x;
            gr5 += zv.x*d1.y; gi5 += zv.y*d1.y;
            gr6 += zv.x*d1.z; gi6 += zv.y*d1.z;
            gr7 += zv.x*d1.w; gi7 += zv.y*d1.w;
            idx += c_hstep[l] + inc;
        }
        int base = m*41 + j;
        Gs[base        ] = make_float2(gr0, gi0);
        Gs[base +  820 ] = make_float2(gr1, gi1);
        Gs[base + 1640 ] = make_float2(gr2, gi2);
        Gs[base + 2460 ] = make_float2(gr3, gi3);
        Gs[base + 3280 ] = make_float2(gr4, gi4);
        Gs[base + 4100 ] = make_float2(gr5, gi5);
        Gs[base + 4920 ] = make_float2(gr6, gi6);
        Gs[base + 5740 ] = make_float2(gr7, gi7);
    }
    __syncthreads();

    // phase 2a: stage-1 FFT partials in registers (reads Gs only)
    int h = t / 160, row = t - h*160;
    int blocR = row / 20, mR = row % 20;
    float2 T[5][4];
    {
        const float2* Grow = Gs + row*41;
        if (h == 0) fft40_T<0>(Grow, T);
        else        fft40_T<1>(Grow, T);
    }
    __syncthreads();   // all Gs reads done; region becomes H

    // phase 2b: combine + write H into smem (pitch 22)
    {
        float2* dsts = Hs + blocR*880 + mR;   // + (8s+u)*22
        #pragma unroll
        for (int up = 0; up < 4; up++) {
            int u = 4*h + up;
            #pragma unroll
            for (int s = 0; s < 5; s++) {
                float2 acc = T[0][up];
                #pragma unroll
                for (int r = 1; r < 5; r++)
                    acc = cadd(acc, cmulc(T[r][up], TWC[(8*r*s)%40], TWS[(8*r*s)%40]));
                dsts[(8*s + u) * 22] = acc;
            }
        }
    }
    __syncthreads();

    // phase 3: stage-2 real FFT per (b, g) column, u/(u+4) radix-2 pairing
    {
        int bloc = t / 40, g = t - bloc*40;
        int b = bg*8 + bloc;
        const float4* col4 = (const float4*)(Hs + (bloc*40 + g)*22);
        float2 hc[20];
        #pragma unroll
        for (int k = 0; k < 10; k++) {
            float4 v = col4[k];
            hc[2*k]   = make_float2(v.x, v.y);
            hc[2*k+1] = make_float2(v.z, v.w);
        }
        hc[0].x *= 0.5f; hc[0].y *= 0.5f;
        float bv = bias[zo & 31];
        float* op = out + (size_t)zo*64000 + b*1600 + g;
        #pragma unroll
        for (int u = 0; u < 4; u++) {
            float2 B0[5], B1[5];
            #pragma unroll
            for (int r = 0; r < 5; r++) {
                float2 h2 = hc[10 + r];
                float2 t2;
                if      (u == 0) t2 = h2;
                else if (u == 1) t2 = cmuli(h2);
                else if (u == 2) t2 = make_float2(-h2.x, -h2.y);
                else             t2 = cmulni(h2);
                float2 P = cadd(hc[r], t2);
                float2 Q = cadd(cmulc(hc[5 + r],  W8C[u],       W8S[u]),
                                cmulc(hc[15 + r], W8C[(3*u)&7], W8S[(3*u)&7]));
                float2 Au = cadd(P, Q);
                float2 Av = csub(P, Q);
                B0[r] = cmulc(Au, TWC[(r*u)%40],     TWS[(r*u)%40]);
                B1[r] = cmulc(Av, TWC[(r*(u+4))%40], TWS[(r*(u+4))%40]);
            }
            #pragma unroll
            for (int s = 0; s < 5; s++) {
                float v0 = B0[0].x, v1 = B1[0].x;
                #pragma unroll
                for (int r = 1; r < 5; r++) {
                    v0 += B0[r].x * TWC[(8*r*s)%40] - B0[r].y * TWS[(8*r*s)%40];
                    v1 += B1[r].x * TWC[(8*r*s)%40] - B1[r].y * TWS[(8*r*s)%40];
                }
                op[(8*s + u    ) * 40] = 2.0f*v0 + bv;
                op[(8*s + u + 4) * 40] = 2.0f*v1 + bv;
            }
        }
    }
}

// ---------- launch ----------
extern "C" void kernel_launch(void* const* d_in, const int* in_sizes, int n_in,
                              void* d_out, int out_size) {
    const float* x    = (const float*)d_in[0];
    const float* kern = (const float*)d_in[1];
    const float* bias = (const float*)d_in[2];
    float* out = (float*)d_out;

    cudaFuncSetAttribute(k_zl, cudaFuncAttributeMaxDynamicSharedMemorySize, 115200);
    cudaFuncSetAttribute(k_ho, cudaFuncAttributeMaxDynamicSharedMemorySize, 56320);

    k_init<<<193, 128>>>();
    k_dft<<<dim3(8, 256), 160>>>(x);
    k_xl2cy<<<dim3(45, 16), 512>>>(kern);
    k_zl <<<dim3(32, 16), 512, 115200>>>();
    k_ho <<<dim3(512, 5), 320, 56320>>>(bias, out);
}